// round 14
// baseline (speedup 1.0000x reference)
#include <cuda_runtime.h>
#include <cuda_fp16.h>
#include <cstdint>

// ---------------- problem constants ----------------
#define B_     8
#define CIN    64
#define COUT   128
#define HP     66
#define WP     66
#define FDIM   448               // 64 ch * 7 features
#define KDIM   4032              // 9 taps * 448
#define NPIX   32768
#define PATCH  576
#define NCHUNK 126               // K chunks of 32
#define HCHUNK 63                // chunks per K-group (63 = 7*9)

#define FEAT_BLOCKS ((B_*HP*WP*16)/256)            // 2178 (4 ch/thread)
#define PACK_BLOCKS ((COUT*KDIM + 255)/256)        // 2016

// ---------------- scratch (device globals) ----------------
__device__ __half   g_Fh[(size_t)B_*HP*WP*FDIM];     // 31.2 MB fp16 features
__device__ uint4    g_Wp[(size_t)COUT*KDIM/8];       // 1 MB weights in mma-frag order
__device__ uint32_t g_offA[NCHUNK];                  // per-chunk A element offsets

// ---------------- PTX helpers ----------------
__device__ __forceinline__ uint32_t smem_u32(const void* p) {
    uint32_t a;
    asm("{ .reg .u64 t; cvta.to.shared.u64 t, %1; cvt.u32.u64 %0, t; }"
        : "=r"(a) : "l"(p));
    return a;
}
__device__ __forceinline__ void cpasync16(uint32_t sa, const void* g) {
    asm volatile("cp.async.cg.shared.global [%0], [%1], 16;"
                 :: "r"(sa), "l"(g) : "memory");
}
__device__ __forceinline__ void cp_commit() {
    asm volatile("cp.async.commit_group;" ::: "memory");
}
__device__ __forceinline__ void cp_wait0() {
    asm volatile("cp.async.wait_group 0;" ::: "memory");
}
__device__ __forceinline__ void bar_grp(int id) {
    asm volatile("bar.sync %0, 128;" :: "r"(id) : "memory");
}
__device__ __forceinline__ void ldsm4(uint32_t* r, uint32_t addr) {
    asm volatile("ldmatrix.sync.aligned.m8n8.x4.shared.b16 {%0,%1,%2,%3}, [%4];"
                 : "=r"(r[0]), "=r"(r[1]), "=r"(r[2]), "=r"(r[3]) : "r"(addr));
}
__device__ __forceinline__ void mma16816(float* d, const uint32_t* a, uint32_t b0, uint32_t b1) {
    asm volatile(
        "mma.sync.aligned.m16n8k16.row.col.f32.f16.f16.f32 "
        "{%0,%1,%2,%3}, {%4,%5,%6,%7}, {%8,%9}, {%0,%1,%2,%3};"
        : "+f"(d[0]), "+f"(d[1]), "+f"(d[2]), "+f"(d[3])
        : "r"(a[0]), "r"(a[1]), "r"(a[2]), "r"(a[3]), "r"(b0), "r"(b1));
}
__device__ __forceinline__ uint32_t h2_bits(float a, float b) {
    half2 h = __floats2half2_rn(a, b);
    return *reinterpret_cast<uint32_t*>(&h);
}

// ---------------- Cox–de Boor features ----------------
__device__ __forceinline__ void eval_features(float v, float* f)
{
    const float hh = 2.0f / 3.0f;
    float g[10];
    #pragma unroll
    for (int j = 0; j < 10; j++) g[j] = (float)(j - 3) * hh - 1.0f;

    float bas[9];
    #pragma unroll
    for (int i = 0; i < 9; i++)
        bas[i] = (v >= g[i] && v < g[i+1]) ? 1.0f : 0.0f;
    const float rp1 = 1.5f, rp2 = 0.75f, rp3 = 0.5f;
    #pragma unroll
    for (int i = 0; i < 8; i++)
        bas[i] = (v - g[i]) * rp1 * bas[i] + (g[i+2] - v) * rp1 * bas[i+1];
    #pragma unroll
    for (int i = 0; i < 7; i++)
        bas[i] = (v - g[i]) * rp2 * bas[i] + (g[i+3] - v) * rp2 * bas[i+1];
    #pragma unroll
    for (int i = 0; i < 6; i++)
        bas[i] = (v - g[i]) * rp3 * bas[i] + (g[i+4] - v) * rp3 * bas[i+1];

    f[0] = v / (1.0f + __expf(-v));   // silu
    #pragma unroll
    for (int m = 0; m < 6; m++) f[m+1] = bas[m];
}

// ---------------- kernel 1: fused feature + weight pack + offset table ----------
// Weight frag layout (R12): frag16 idx = ((chunk*4 + wn)*4 + nt)*32 + lane
//   wn = o>>5 (32-col group), nt = (o>>3)&3, lane = (o&7)*4 + ((k&7)>>1)
//   pos = ((k>>4)&1)*4 + ((k>>3)&1)*2 + (k&1), chunk = k>>5
__global__ void prep_kernel(const float* __restrict__ x,
                            const float* __restrict__ base_w,
                            const float* __restrict__ spline_w)
{
    if (blockIdx.x < FEAT_BLOCKS) {
        int idx = blockIdx.x * blockDim.x + threadIdx.x;  // (pixel, channel-quad)
        int cq = idx & 15;
        int r  = idx >> 4;
        int wp = r % WP; r /= WP;
        int hp = r % HP;
        int b  = r / HP;

        int h = hp - 1, w = wp - 1;
        float4 xv = make_float4(0.f, 0.f, 0.f, 0.f);
        if (h >= 0 && h < 64 && w >= 0 && w < 64)
            xv = *(const float4*)&x[((((size_t)b*64 + h)*64 + w) << 6) + cq*4];

        float f0[7], f1[7], f2[7], f3[7];
        eval_features(xv.x, f0);
        eval_features(xv.y, f1);
        eval_features(xv.z, f2);
        eval_features(xv.w, f3);

        size_t base = (((size_t)b*HP + hp)*WP + wp)*FDIM + cq*4;
        #pragma unroll
        for (int m = 0; m < 7; m++) {
            uint2 pk;
            pk.x = h2_bits(f0[m], f1[m]);
            pk.y = h2_bits(f2[m], f3[m]);
            *(uint2*)&g_Fh[base + (size_t)m*64] = pk;
        }
    } else if (blockIdx.x < FEAT_BLOCKS + PACK_BLOCKS) {
        int idx = (blockIdx.x - FEAT_BLOCKS) * blockDim.x + threadIdx.x; // o*4032+k
        if (idx >= COUT * KDIM) return;
        int o = idx / KDIM;
        int k = idx - o * KDIM;
        int t = k / FDIM;
        int rr = k - t * FDIM;
        int f  = rr >> 6;
        int cc = rr & 63;
        int i  = cc * 9 + t;
        float wv = (f == 0) ? base_w[(size_t)o * PATCH + i]
                            : spline_w[((size_t)o * PATCH + i) * 6 + (f - 1)];

        int chunk = k >> 5;
        int wn    = o >> 5;
        int nt    = (o >> 3) & 3;
        int lane  = ((o & 7) << 2) | ((k & 7) >> 1);
        int pos   = ((k >> 4) & 1) * 4 + ((k >> 3) & 1) * 2 + (k & 1);
        size_t idx16 = (((size_t)chunk*4 + wn)*4 + nt)*32 + lane;
        ((__half*)g_Wp)[idx16 * 8 + pos] = __float2half(wv);
    } else {
        int c = threadIdx.x;
        if (c < NCHUNK) {
            int t  = c / 14;
            int rr = c - t * 14;
            int f  = rr >> 1;
            int c0 = (rr & 1) << 5;
            int ky = t / 3;
            int kx = t - ky * 3;
            g_offA[c] = (uint32_t)((ky * WP + kx) * FDIM + f * 64 + c0);
        }
    }
}

// ---------------- kernel 2: GEMM, M32xN128, split-K, SW-pipelined frags --------
// 1024 CTAs x 256 threads, 2 CTAs/SM. CTA tile: M=32, N=128, K=4032.
// 8 warps = 2 K-groups x 4 N-warps; warp tile M32 x N32 (acc 32 regs).
// A-frags and B-frags double-buffered one chunk ahead in registers; 9-slot
// smem A pipeline; wait_group 0 + named barrier once per 3-chunk window.
#define NSLOT  9
#define PITCH  80
#define STAGEB (32*PITCH)                 // 2560 B
#define REGION (NSLOT*STAGEB)             // 23040 B per K-group
#define RED_PITCH 132
#define DYN_SMEM (2*REGION)               // 46080 B (> 32*132*4 = 16896 epilogue)

__global__ void __launch_bounds__(256, 2)
gemm_kernel(const float* __restrict__ bias, float* __restrict__ out)
{
    extern __shared__ char dyn[];
    const uint32_t smbase = smem_u32(dyn);

    const int tid  = threadIdx.x;
    const int wid  = tid >> 5;
    const int lane = tid & 31;
    const int ks   = wid >> 2;              // K-group 0/1
    const int wn   = wid & 3;               // 32-col N group

    const int pixBase = blockIdx.x * 32;
    const int bimg    = pixBase >> 12;
    const int h0      = (pixBase >> 6) & 63;
    const int w0      = pixBase & 63;

    // ---- A cp.async geometry: each K-group's 128 threads load their own chunk
    const int rrow = (tid & 127) >> 2;      // 0..31
    const int seg  = tid & 3;
    const uint32_t baseA = (uint32_t)((((bimg*HP + h0)*WP) + (w0 + rrow))*FDIM) + seg*8;
    const uint32_t dstA  = smbase + ks * REGION + rrow * PITCH + seg * 16;

    // ---- A ldmatrix geometry (4 warps of a K-group share the same fragments)
    const uint32_t pA = smbase + ks * REGION + (lane & 15) * PITCH + (lane >> 4) * 16;

    // ---- B LDG geometry: frag16 idx = ((chunk*4 + wn)*4 + nt)*32 + lane
    const uint4* wpBase = g_Wp + (size_t)wn * 128 + lane;   // chunk stride 512, nt +32
    const int cBase = ks * HCHUNK;

    float acc[2][4][4];
    #pragma unroll
    for (int mt = 0; mt < 2; mt++)
        #pragma unroll
        for (int nt = 0; nt < 4; nt++)
            #pragma unroll
            for (int q = 0; q < 4; q++) acc[mt][nt][q] = 0.0f;

    auto produce = [&](int i, int s) {
        const uint32_t off = g_offA[cBase + i];
        cpasync16(dstA + s * STAGEB, g_Fh + baseA + off);
    };

    const int barid = ks + 1;

    // window sync: wait ALL outstanding A groups, group barrier, produce next
    auto syncprod = [&](int wc, int sb) {
        cp_wait0();
        bar_grp(barid);
        if (wc + 6 < HCHUNK) {
            produce(wc + 6, sb);
            produce(wc + 7, sb + 1);
            produce(wc + 8, sb + 2);
        }
        cp_commit();
    };

    // frag double buffers: a[p][4 frags][4 regs], b[p][4 uint4]
    uint32_t aB[2][4][4];
    uint4    bB[2][4];

    // load A frags for chunk i from slot s into buffer p
    auto ldA = [&](int p, int s) {
        const uint32_t so = pA + s * STAGEB;
        ldsm4(aB[p][0], so);                  // mt=0, kk=0
        ldsm4(aB[p][1], so + 16*PITCH);       // mt=1, kk=0
        ldsm4(aB[p][2], so + 32);             // mt=0, kk=1
        ldsm4(aB[p][3], so + 16*PITCH + 32);  // mt=1, kk=1
    };
    auto ldB = [&](int p, int i) {
        if (i < HCHUNK) {
            const uint4* w = wpBase + (size_t)(cBase + i) * 512;
            #pragma unroll
            for (int nt = 0; nt < 4; nt++) bB[p][nt] = w[nt * 32];
        }
    };

    // body: prefetch chunk i+1 (slot spf) into buffer p^1, compute chunk i from p
    auto body = [&](int i, int spf, int p) {
        ldB(p ^ 1, i + 1);
        ldA(p ^ 1, spf);
        #pragma unroll
        for (int nt = 0; nt < 4; nt++) {
            mma16816(acc[0][nt], aB[p][0], bB[p][nt].x, bB[p][nt].y);
            mma16816(acc[1][nt], aB[p][1], bB[p][nt].x, bB[p][nt].y);
        }
        #pragma unroll
        for (int nt = 0; nt < 4; nt++) {
            mma16816(acc[0][nt], aB[p][2], bB[p][nt].z, bB[p][nt].w);
            mma16816(acc[1][nt], aB[p][3], bB[p][nt].z, bB[p][nt].w);
        }
    };

    // ---- prologue: stage chunks 0..5, sync window 0, produce 6..8, preload ----
    produce(0, 0); produce(1, 1); produce(2, 2); cp_commit();
    produce(3, 3); produce(4, 4); produce(5, 5); cp_commit();
    syncprod(0, 6);          // waits chunks 0..5, produces 6..8
    ldA(0, 0);
    ldB(0, 0);

    #pragma unroll 1
    for (int w = 0; w < HCHUNK; w += 9) {   // 63 = 7 * 9
        body(w + 0, 1, 0);
        body(w + 1, 2, 1);
        body(w + 2, 3, 0);
        syncprod(w + 3, 0);
        body(w + 3, 4, 1);
        body(w + 4, 5, 0);
        body(w + 5, 6, 1);
        syncprod(w + 6, 3);
        body(w + 6, 7, 0);
        body(w + 7, 8, 1);
        body(w + 8, 0, 0);                  // prefetches chunk w+9 from slot 0
        if (w + 9 < HCHUNK) syncprod(w + 9, 6);
        // parity fix: bodies ended with next-chunk data in buffer 1 -> buffer 0
        #pragma unroll
        for (int fq = 0; fq < 4; fq++) {
            #pragma unroll
            for (int q = 0; q < 4; q++) aB[0][fq][q] = aB[1][fq][q];
            bB[0][fq] = bB[1][fq];
        }
    }

    // ---- epilogue: reduce the two K-group partials via smem, + bias, store ----
    __syncthreads();
    float* red = (float*)dyn;   // [32][RED_PITCH]
    const int colb0 = wn*32 + (lane & 3)*2;
    const int row0  = lane >> 2;

    if (ks == 1) {
        #pragma unroll
        for (int mt = 0; mt < 2; mt++)
            #pragma unroll
            for (int nt = 0; nt < 4; nt++) {
                const int col = colb0 + nt*8;
                *(float2*)&red[(mt*16 + row0    ) * RED_PITCH + col] =
                    make_float2(acc[mt][nt][0], acc[mt][nt][1]);
                *(float2*)&red[(mt*16 + row0 + 8) * RED_PITCH + col] =
                    make_float2(acc[mt][nt][2], acc[mt][nt][3]);
            }
    }
    __syncthreads();
    if (ks == 0) {
        #pragma unroll
        for (int mt = 0; mt < 2; mt++)
            #pragma unroll
            for (int nt = 0; nt < 4; nt++) {
                const int col = colb0 + nt*8;
                const float2 b2 = *(const float2*)(bias + col);
                float2 p0 = *(float2*)&red[(mt*16 + row0    ) * RED_PITCH + col];
                float2 p1 = *(float2*)&red[(mt*16 + row0 + 8) * RED_PITCH + col];
                float2 v0, v1;
                v0.x = acc[mt][nt][0] + p0.x + b2.x;
                v0.y = acc[mt][nt][1] + p0.y + b2.y;
                v1.x = acc[mt][nt][2] + p1.x + b2.x;
                v1.y = acc[mt][nt][3] + p1.y + b2.y;
                const int prow = pixBase + mt*16 + row0;
                *(float2*)(out + (size_t)prow      *COUT + col) = v0;
                *(float2*)(out + (size_t)(prow + 8)*COUT + col) = v1;
            }
    }
}

// ---------------- launch ----------------
extern "C" void kernel_launch(void* const* d_in, const int* in_sizes, int n_in,
                              void* d_out, int out_size)
{
    const float *x = nullptr, *bw = nullptr, *sw = nullptr, *bs = nullptr;
    for (int i = 0; i < n_in; i++) {
        switch (in_sizes[i]) {
            case 8*64*64*64:   x  = (const float*)d_in[i]; break;
            case COUT*PATCH:   bw = (const float*)d_in[i]; break;
            case COUT*PATCH*6: sw = (const float*)d_in[i]; break;
            case COUT:         bs = (const float*)d_in[i]; break;
        }
    }
    float* out = (float*)d_out;

    prep_kernel<<<FEAT_BLOCKS + PACK_BLOCKS + 1, 256>>>(x, bw, sw);
    gemm_kernel<<<NPIX / 32, 256, DYN_SMEM>>>(bs, out);
}